// round 12
// baseline (speedup 1.0000x reference)
#include <cuda_runtime.h>
#include <cuda_fp16.h>
#include <cuda_bf16.h>
#include <cstdint>

#define N_NODES 50000
#define N_EDGES 800000
#define HID 256
#define NG 128
#define NBLK 196          // ceil(N_NODES/256)

// ---- scratch (static device globals; no allocation) ----
__device__ int    g_deg[N_NODES];
__device__ int    g_rowptr[N_NODES];
__device__ int    g_cursor[N_NODES];
__device__ int    g_eidx[N_EDGES];
__device__ int    g_bsum[NBLK];
__device__ int    g_boff[NBLK];
__device__ float  g_dinv[N_NODES];
__device__ float  g_px[N_NODES * 2];
__device__ float  g_h[(size_t)N_NODES * HID];
__device__ __half g_ph[(size_t)N_NODES * HID];   // p in fp16 (halves gather traffic)
__device__ float  g_agg[(size_t)N_NODES * HID];
__device__ float  g_pool[NG * HID];

__device__ __forceinline__ uint32_t f2tf32(float x) {
    uint32_t r;
    asm("cvt.rna.tf32.f32 %0, %1;" : "=r"(r) : "f"(x));
    return r;
}

// unpack uint4 (8 halves) and add into 8 fp32 accumulators
__device__ __forceinline__ void h8_add(float* acc, uint4 v) {
    const __half2* h = (const __half2*)&v;
#pragma unroll
    for (int i = 0; i < 4; i++) {
        float2 f = __half22float2(h[i]);
        acc[2 * i] += f.x;
        acc[2 * i + 1] += f.y;
    }
}

// ---- zero degrees ----
__global__ void k_zero() {
    int i = blockIdx.x * blockDim.x + threadIdx.x;
    if (i < N_NODES) g_deg[i] = 0;
}

__global__ void k_count(const int* __restrict__ ei) {
    int e = blockIdx.x * blockDim.x + threadIdx.x;
    if (e < N_EDGES) atomicAdd(&g_deg[ei[N_EDGES + e]], 1);
}

// dinv = rsqrt(deg+1); px = dinv * x  (fused)
__global__ void k_rsqrt_px(const float* __restrict__ x) {
    int i = blockIdx.x * blockDim.x + threadIdx.x;
    if (i < N_NODES) {
        float d = rsqrtf((float)g_deg[i] + 1.0f);
        g_dinv[i] = d;
        float2 v = ((const float2*)x)[i];
        float2 o; o.x = d * v.x; o.y = d * v.y;
        ((float2*)g_px)[i] = o;
    }
}

// ---- CSR build: parallel two-level exclusive scan ----
__global__ void k_blocksum() {
    __shared__ int s[256];
    int t = threadIdx.x;
    int i = blockIdx.x * 256 + t;
    int v = (i < N_NODES) ? g_deg[i] : 0;
    s[t] = v; __syncthreads();
    for (int o = 128; o; o >>= 1) { if (t < o) s[t] += s[t + o]; __syncthreads(); }
    if (t == 0) g_bsum[blockIdx.x] = s[0];
}

__global__ void k_scanb() {  // single block, exclusive scan of NBLK block sums
    __shared__ int s[256];
    int t = threadIdx.x;
    int v = (t < NBLK) ? g_bsum[t] : 0;
    s[t] = v; __syncthreads();
    for (int o = 1; o < 256; o <<= 1) {
        int x = (t >= o) ? s[t - o] : 0; __syncthreads();
        s[t] += x; __syncthreads();
    }
    if (t < NBLK) g_boff[t] = s[t] - v;  // exclusive
}

__global__ void k_scan3() {
    __shared__ int s[256];
    int t = threadIdx.x;
    int i = blockIdx.x * 256 + t;
    int v = (i < N_NODES) ? g_deg[i] : 0;
    s[t] = v; __syncthreads();
    for (int o = 1; o < 256; o <<= 1) {
        int x = (t >= o) ? s[t - o] : 0; __syncthreads();
        s[t] += x; __syncthreads();
    }
    if (i < N_NODES) {
        int beg = g_boff[blockIdx.x] + s[t] - v;
        g_rowptr[i] = beg;
        g_cursor[i] = beg;
    }
}

__global__ void k_fill(const int* __restrict__ ei) {
    int e = blockIdx.x * blockDim.x + threadIdx.x;
    if (e < N_EDGES) {
        int d = ei[N_EDGES + e];
        int pos = atomicAdd(&g_cursor[d], 1);
        g_eidx[pos] = ei[e];
    }
}

// ---- layer 1: block per node; warp 0 gathers 2-wide, fused transform ----
__global__ void k_layer1(const float* __restrict__ W1, const float* __restrict__ b1) {
    __shared__ float sa[2];
    int i = blockIdx.x;
    int t = threadIdx.x;  // 256
    if (t < 32) {
        int beg = g_rowptr[i], n = g_deg[i];
        float a = 0.f, b = 0.f;
        for (int e = t; e < n; e += 32) {
            int s = g_eidx[beg + e];
            a += g_px[2 * s];
            b += g_px[2 * s + 1];
        }
#pragma unroll
        for (int o = 16; o; o >>= 1) {
            a += __shfl_down_sync(0xffffffffu, a, o);
            b += __shfl_down_sync(0xffffffffu, b, o);
        }
        if (t == 0) { sa[0] = a + g_px[2 * i]; sa[1] = b + g_px[2 * i + 1]; }
    }
    __syncthreads();
    float d = g_dinv[i];
    float a0 = sa[0] * d;
    float a1 = sa[1] * d;
    float h = a0 * W1[t] + a1 * W1[HID + t] + b1[t];
    g_ph[(size_t)i * HID + t] = __float2half_rn(fmaxf(h, 0.f) * d);
}

// ---- CSR gather: 1 warp per dst node, fp16 rows (1 LDG.128/lane/edge),
//      fp32 accumulation, fp32 agg output ----
__global__ void k_gather() {
    int w = (blockIdx.x * blockDim.x + threadIdx.x) >> 5;
    int l = threadIdx.x & 31;
    if (w >= N_NODES) return;
    int beg = g_rowptr[w], n = g_deg[w];
    float acc[8] = {};
    // self-loop init
    h8_add(acc, ((const uint4*)(g_ph + (size_t)w * HID))[l]);
    int e = 0;
    for (; e + 2 <= n; e += 2) {
        int s0 = g_eidx[beg + e];
        int s1 = g_eidx[beg + e + 1];
        uint4 v0 = __ldg((const uint4*)(g_ph + (size_t)s0 * HID) + l);
        uint4 v1 = __ldg((const uint4*)(g_ph + (size_t)s1 * HID) + l);
        h8_add(acc, v0);
        h8_add(acc, v1);
    }
    if (e < n) {
        int s0 = g_eidx[beg + e];
        h8_add(acc, __ldg((const uint4*)(g_ph + (size_t)s0 * HID) + l));
    }
    float4* ad = (float4*)(g_agg + (size_t)w * HID + 8 * l);
    ad[0] = make_float4(acc[0], acc[1], acc[2], acc[3]);
    ad[1] = make_float4(acc[4], acc[5], acc[6], acc[7]);
}

// ---- TF32 tensor-core GEMM: out = (dinv⊙agg)@W + bias ----
// Block 128x128, 8 warps (2 M x 4 N), warp tile 64x32 as 4x4 mma m16n8k8.
// WRITE_P: out = relu(h)*dinv -> fp16 g_ph (layers 2,3); else fp32 g_h (layer 4)
#define AS_STRIDE 36   // 32 + 4 pad -> A-frag banks = 4g+q  (conflict-free)
#define BS_STRIDE 136  // 128 + 8 pad -> B-frag banks = 8q+g (conflict-free)
template <bool WRITE_P>
__global__ void __launch_bounds__(256, 2) k_gemm(const float* __restrict__ W,
                                                 const float* __restrict__ bias) {
    __shared__ uint32_t As[128 * AS_STRIDE];  // [m][k] tf32, 18432 B
    __shared__ uint32_t Bs[32 * BS_STRIDE];   // [k][n] tf32, 17408 B
    int tid = threadIdx.x;
    int lane = tid & 31;
    int warp = tid >> 5;
    int warp_m = warp & 1;        // 0..1
    int warp_n = warp >> 1;       // 0..3
    int g = lane >> 2;            // 0..7
    int q = lane & 3;             // 0..3
    int rowBase = blockIdx.y * 128;
    int colBase = blockIdx.x * 128;

    float c[4][4][4];             // [mi][ni][reg]
#pragma unroll
    for (int mi = 0; mi < 4; mi++)
#pragma unroll
        for (int ni = 0; ni < 4; ni++)
#pragma unroll
            for (int r = 0; r < 4; r++) c[mi][ni][r] = 0.f;

    for (int k0 = 0; k0 < HID; k0 += 32) {
        // A tile: 128x32 floats -> tf32, [m][k] padded
        {
            int m0 = tid >> 3;          // 0..31
            int kq = (tid & 7) * 4;     // 0,4,..28
#pragma unroll
            for (int i = 0; i < 4; i++) {
                int m = m0 + i * 32;
                int gr = rowBase + m;
                float4 v = (gr < N_NODES)
                    ? *(const float4*)&g_agg[(size_t)gr * HID + k0 + kq]
                    : make_float4(0.f, 0.f, 0.f, 0.f);
                uint32_t* dst = &As[m * AS_STRIDE + kq];
                dst[0] = f2tf32(v.x); dst[1] = f2tf32(v.y);
                dst[2] = f2tf32(v.z); dst[3] = f2tf32(v.w);
            }
        }
        // B tile: 32 k x 128 n floats -> tf32, [k][n] padded
        {
            int kk = tid >> 3;          // 0..31
            int nq = (tid & 7) * 4;
#pragma unroll
            for (int i = 0; i < 4; i++) {
                int n = nq + i * 32;
                float4 v = *(const float4*)&W[(size_t)(k0 + kk) * HID + colBase + n];
                uint32_t* dst = &Bs[kk * BS_STRIDE + n];
                dst[0] = f2tf32(v.x); dst[1] = f2tf32(v.y);
                dst[2] = f2tf32(v.z); dst[3] = f2tf32(v.w);
            }
        }
        __syncthreads();

#pragma unroll
        for (int ks = 0; ks < 4; ks++) {   // 4 k-steps of 8
            int kb = ks * 8;
            uint32_t a[4][4], b[4][2];
#pragma unroll
            for (int mi = 0; mi < 4; mi++) {
                int m = warp_m * 64 + mi * 16;
                const uint32_t* ap = &As[(m + g) * AS_STRIDE + kb + q];
                a[mi][0] = ap[0];
                a[mi][1] = ap[8 * AS_STRIDE];
                a[mi][2] = ap[4];
                a[mi][3] = ap[8 * AS_STRIDE + 4];
            }
#pragma unroll
            for (int ni = 0; ni < 4; ni++) {
                int n = warp_n * 32 + ni * 8;
                const uint32_t* bp = &Bs[(kb + q) * BS_STRIDE + n + g];
                b[ni][0] = bp[0];
                b[ni][1] = bp[4 * BS_STRIDE];
            }
#pragma unroll
            for (int mi = 0; mi < 4; mi++)
#pragma unroll
                for (int ni = 0; ni < 4; ni++) {
                    asm volatile(
                        "mma.sync.aligned.m16n8k8.row.col.f32.tf32.tf32.f32 "
                        "{%0,%1,%2,%3}, {%4,%5,%6,%7}, {%8,%9}, {%0,%1,%2,%3};"
                        : "+f"(c[mi][ni][0]), "+f"(c[mi][ni][1]),
                          "+f"(c[mi][ni][2]), "+f"(c[mi][ni][3])
                        : "r"(a[mi][0]), "r"(a[mi][1]), "r"(a[mi][2]), "r"(a[mi][3]),
                          "r"(b[ni][0]), "r"(b[ni][1]));
                }
        }
        __syncthreads();
    }

    // epilogue: c[mi][ni] regs map to rows (m+g, m+g+8), cols (n+2q, n+2q+1)
#pragma unroll
    for (int mi = 0; mi < 4; mi++) {
#pragma unroll
        for (int half = 0; half < 2; half++) {
            int r = rowBase + warp_m * 64 + mi * 16 + g + half * 8;
            if (r >= N_NODES) continue;
            float d = g_dinv[r];
#pragma unroll
            for (int ni = 0; ni < 4; ni++) {
                int cc = colBase + warp_n * 32 + ni * 8 + 2 * q;
                float v0 = d * c[mi][ni][half * 2 + 0] + bias[cc];
                float v1 = d * c[mi][ni][half * 2 + 1] + bias[cc + 1];
                if (WRITE_P) {
                    v0 = fmaxf(v0, 0.f) * d;
                    v1 = fmaxf(v1, 0.f) * d;
                    *(__half2*)&g_ph[(size_t)r * HID + cc] = __floats2half2_rn(v0, v1);
                } else {
                    *(float2*)&g_h[(size_t)r * HID + cc] = make_float2(v0, v1);
                }
            }
        }
    }
}

// ---- mean pool: block per graph, binary-search bounds (batch sorted),
//      row loop unrolled x4 for MLP ----
__global__ void k_pool(const int* __restrict__ batch) {
    int g = blockIdx.x;
    int j = threadIdx.x;  // 256
    int a = 0, b = N_NODES;
    while (a < b) { int m = (a + b) >> 1; if (batch[m] < g) a = m + 1; else b = m; }
    int lo = a;
    b = N_NODES;
    while (a < b) { int m = (a + b) >> 1; if (batch[m] < g + 1) a = m + 1; else b = m; }
    int hi = a;
    float s0 = 0.f, s1 = 0.f, s2 = 0.f, s3 = 0.f;
    int r = lo;
    for (; r + 4 <= hi; r += 4) {
        s0 += g_h[(size_t)(r + 0) * HID + j];
        s1 += g_h[(size_t)(r + 1) * HID + j];
        s2 += g_h[(size_t)(r + 2) * HID + j];
        s3 += g_h[(size_t)(r + 3) * HID + j];
    }
    for (; r < hi; r++) s0 += g_h[(size_t)r * HID + j];
    float acc = (s0 + s1) + (s2 + s3);
    g_pool[g * HID + j] = acc / fmaxf((float)(hi - lo), 1.f);
}

// ---- head: lin1+relu, lin2 ----
__global__ void k_head(const float* __restrict__ l1w, const float* __restrict__ l1b,
                       const float* __restrict__ l2w, const float* __restrict__ l2b,
                       float* __restrict__ out) {
    __shared__ float gv[HID];
    __shared__ float red[4];
    int g = blockIdx.x, t = threadIdx.x;  // 128 threads
    gv[t] = g_pool[g * HID + t];
    gv[t + 128] = g_pool[g * HID + t + 128];
    __syncthreads();
    float acc = l1b[t];
#pragma unroll 8
    for (int k = 0; k < HID; k++) acc += gv[k] * l1w[k * 128 + t];
    acc = fmaxf(acc, 0.f) * l2w[t];
#pragma unroll
    for (int o = 16; o; o >>= 1) acc += __shfl_down_sync(0xffffffffu, acc, o);
    if ((t & 31) == 0) red[t >> 5] = acc;
    __syncthreads();
    if (t == 0) out[g] = red[0] + red[1] + red[2] + red[3] + l2b[0];
}

extern "C" void kernel_launch(void* const* d_in, const int* in_sizes, int n_in,
                              void* d_out, int out_size) {
    const float* x     = (const float*)d_in[0];
    const int* ei      = (const int*)d_in[1];   // int32 (JAX x32 mode)
    const int* bat     = (const int*)d_in[2];   // int32
    const float* W1 = (const float*)d_in[3];
    const float* b1 = (const float*)d_in[4];
    const float* Wl[3] = {(const float*)d_in[5], (const float*)d_in[7], (const float*)d_in[9]};
    const float* bl[3] = {(const float*)d_in[6], (const float*)d_in[8], (const float*)d_in[10]};
    const float* l1w = (const float*)d_in[11];
    const float* l1b = (const float*)d_in[12];
    const float* l2w = (const float*)d_in[13];
    const float* l2b = (const float*)d_in[14];
    float* out = (float*)d_out;

    // degrees + norm + CSR (dst-major), parallel scan
    k_zero<<<(N_NODES + 255) / 256, 256>>>();
    k_count<<<(N_EDGES + 255) / 256, 256>>>(ei);
    k_rsqrt_px<<<(N_NODES + 255) / 256, 256>>>(x);
    k_blocksum<<<NBLK, 256>>>();
    k_scanb<<<1, 256>>>();
    k_scan3<<<NBLK, 256>>>();
    k_fill<<<(N_EDGES + 255) / 256, 256>>>(ei);

    // layer 1: fused 2-wide gather + 2->256 transform + relu*dinv prep (fp16 out)
    k_layer1<<<N_NODES, 256>>>(W1, b1);

    // layers 2..4: fp16 CSR gather + tf32 tensor-core GEMM with fused epilogue
    dim3 ggrid(HID / 128, (N_NODES + 127) / 128);
    k_gather<<<(N_NODES * 32 + 255) / 256, 256>>>();
    k_gemm<true><<<ggrid, 256>>>(Wl[0], bl[0]);
    k_gather<<<(N_NODES * 32 + 255) / 256, 256>>>();
    k_gemm<true><<<ggrid, 256>>>(Wl[1], bl[1]);
    k_gather<<<(N_NODES * 32 + 255) / 256, 256>>>();
    k_gemm<false><<<ggrid, 256>>>(Wl[2], bl[2]);

    // mean pool (no atomics) + MLP head
    k_pool<<<NG, 256>>>(bat);
    k_head<<<NG, 128>>>(l1w, l1b, l2w, l2b, out);
}

// round 15
// speedup vs baseline: 1.4506x; 1.4506x over previous
#include <cuda_runtime.h>
#include <cuda_fp16.h>
#include <cuda_bf16.h>
#include <cstdint>

#define N_NODES 50000
#define N_EDGES 800000
#define HID 256
#define NG 128
#define NBLK 196          // ceil(N_NODES/256)

// ---- scratch (static device globals; no allocation) ----
__device__ int    g_deg[N_NODES];
__device__ int    g_rowptr[N_NODES];
__device__ int    g_cursor[N_NODES];
__device__ int    g_eidx[N_EDGES];
__device__ int    g_bsum[NBLK];
__device__ int    g_boff[NBLK];
__device__ float  g_dinv[N_NODES];
__device__ float  g_px[N_NODES * 2];
__device__ float  g_h[(size_t)N_NODES * HID];
__device__ __half g_ph[(size_t)N_NODES * HID];   // p in fp16 (halves gather traffic)
__device__ float  g_agg[(size_t)N_NODES * HID];
__device__ float  g_pool[NG * HID];

__device__ __forceinline__ uint32_t f2tf32(float x) {
    uint32_t r;
    asm("cvt.rna.tf32.f32 %0, %1;" : "=r"(r) : "f"(x));
    return r;
}

// unpack uint4 (8 halves) and add into 8 fp32 accumulators
__device__ __forceinline__ void h8_add(float* acc, uint4 v) {
    const __half2* h = (const __half2*)&v;
#pragma unroll
    for (int i = 0; i < 4; i++) {
        float2 f = __half22float2(h[i]);
        acc[2 * i] += f.x;
        acc[2 * i + 1] += f.y;
    }
}

// ---- zero degrees ----
__global__ void k_zero() {
    int i = blockIdx.x * blockDim.x + threadIdx.x;
    if (i < N_NODES) g_deg[i] = 0;
}

__global__ void k_count(const int* __restrict__ ei) {
    int e = blockIdx.x * blockDim.x + threadIdx.x;
    if (e < N_EDGES) atomicAdd(&g_deg[ei[N_EDGES + e]], 1);
}

// dinv = rsqrt(deg+1); px = dinv * x  (fused)
__global__ void k_rsqrt_px(const float* __restrict__ x) {
    int i = blockIdx.x * blockDim.x + threadIdx.x;
    if (i < N_NODES) {
        float d = rsqrtf((float)g_deg[i] + 1.0f);
        g_dinv[i] = d;
        float2 v = ((const float2*)x)[i];
        float2 o; o.x = d * v.x; o.y = d * v.y;
        ((float2*)g_px)[i] = o;
    }
}

// ---- CSR build: parallel two-level exclusive scan ----
__global__ void k_blocksum() {
    __shared__ int s[256];
    int t = threadIdx.x;
    int i = blockIdx.x * 256 + t;
    int v = (i < N_NODES) ? g_deg[i] : 0;
    s[t] = v; __syncthreads();
    for (int o = 128; o; o >>= 1) { if (t < o) s[t] += s[t + o]; __syncthreads(); }
    if (t == 0) g_bsum[blockIdx.x] = s[0];
}

__global__ void k_scanb() {  // single block, exclusive scan of NBLK block sums
    __shared__ int s[256];
    int t = threadIdx.x;
    int v = (t < NBLK) ? g_bsum[t] : 0;
    s[t] = v; __syncthreads();
    for (int o = 1; o < 256; o <<= 1) {
        int x = (t >= o) ? s[t - o] : 0; __syncthreads();
        s[t] += x; __syncthreads();
    }
    if (t < NBLK) g_boff[t] = s[t] - v;  // exclusive
}

__global__ void k_scan3() {
    __shared__ int s[256];
    int t = threadIdx.x;
    int i = blockIdx.x * 256 + t;
    int v = (i < N_NODES) ? g_deg[i] : 0;
    s[t] = v; __syncthreads();
    for (int o = 1; o < 256; o <<= 1) {
        int x = (t >= o) ? s[t - o] : 0; __syncthreads();
        s[t] += x; __syncthreads();
    }
    if (i < N_NODES) {
        int beg = g_boff[blockIdx.x] + s[t] - v;
        g_rowptr[i] = beg;
        g_cursor[i] = beg;
    }
}

__global__ void k_fill(const int* __restrict__ ei) {
    int e = blockIdx.x * blockDim.x + threadIdx.x;
    if (e < N_EDGES) {
        int d = ei[N_EDGES + e];
        int pos = atomicAdd(&g_cursor[d], 1);
        g_eidx[pos] = ei[e];
    }
}

// ---- layer 1: block per node; warp 0 gathers 2-wide, fused transform ----
__global__ void k_layer1(const float* __restrict__ W1, const float* __restrict__ b1) {
    __shared__ float sa[2];
    int i = blockIdx.x;
    int t = threadIdx.x;  // 256
    if (t < 32) {
        int beg = g_rowptr[i], n = g_deg[i];
        float a = 0.f, b = 0.f;
        for (int e = t; e < n; e += 32) {
            int s = g_eidx[beg + e];
            a += g_px[2 * s];
            b += g_px[2 * s + 1];
        }
#pragma unroll
        for (int o = 16; o; o >>= 1) {
            a += __shfl_down_sync(0xffffffffu, a, o);
            b += __shfl_down_sync(0xffffffffu, b, o);
        }
        if (t == 0) { sa[0] = a + g_px[2 * i]; sa[1] = b + g_px[2 * i + 1]; }
    }
    __syncthreads();
    float d = g_dinv[i];
    float a0 = sa[0] * d;
    float a1 = sa[1] * d;
    float h = a0 * W1[t] + a1 * W1[HID + t] + b1[t];
    g_ph[(size_t)i * HID + t] = __float2half_rn(fmaxf(h, 0.f) * d);
}

// ---- CSR gather: 1 warp per dst node, fp16 rows (1 LDG.128/lane/edge),
//      8-edge unroll -> 8 LDG.128 in flight per lane; fp32 accumulation ----
__global__ void k_gather() {
    int w = (blockIdx.x * blockDim.x + threadIdx.x) >> 5;
    int l = threadIdx.x & 31;
    if (w >= N_NODES) return;
    int beg = g_rowptr[w], n = g_deg[w];
    float acc[8] = {};
    // self-loop init
    h8_add(acc, ((const uint4*)(g_ph + (size_t)w * HID))[l]);
    int e = 0;
    for (; e + 8 <= n; e += 8) {
        uint4 v[8];
#pragma unroll
        for (int j = 0; j < 8; j++) {
            int s = g_eidx[beg + e + j];  // broadcast load
            v[j] = __ldg((const uint4*)(g_ph + (size_t)s * HID) + l);
        }
#pragma unroll
        for (int j = 0; j < 8; j++) h8_add(acc, v[j]);
    }
    if (e + 4 <= n) {
        uint4 v[4];
#pragma unroll
        for (int j = 0; j < 4; j++) {
            int s = g_eidx[beg + e + j];
            v[j] = __ldg((const uint4*)(g_ph + (size_t)s * HID) + l);
        }
#pragma unroll
        for (int j = 0; j < 4; j++) h8_add(acc, v[j]);
        e += 4;
    }
    for (; e < n; e++) {
        int s = g_eidx[beg + e];
        h8_add(acc, __ldg((const uint4*)(g_ph + (size_t)s * HID) + l));
    }
    float4* ad = (float4*)(g_agg + (size_t)w * HID + 8 * l);
    ad[0] = make_float4(acc[0], acc[1], acc[2], acc[3]);
    ad[1] = make_float4(acc[4], acc[5], acc[6], acc[7]);
}

// ---- TF32 tensor-core GEMM: out = (dinv⊙agg)@W + bias ----
// Block 128x128, 8 warps (2 M x 4 N), warp tile 64x32 as 4x4 mma m16n8k8.
// WRITE_P: out = relu(h)*dinv -> fp16 g_ph (layers 2,3); else fp32 g_h (layer 4)
#define AS_STRIDE 36   // 32 + 4 pad -> A-frag banks = 4g+q  (conflict-free)
#define BS_STRIDE 136  // 128 + 8 pad -> B-frag banks = 8q+g (conflict-free)
template <bool WRITE_P>
__global__ void __launch_bounds__(256, 2) k_gemm(const float* __restrict__ W,
                                                 const float* __restrict__ bias) {
    __shared__ uint32_t As[128 * AS_STRIDE];  // [m][k] tf32, 18432 B
    __shared__ uint32_t Bs[32 * BS_STRIDE];   // [k][n] tf32, 17408 B
    int tid = threadIdx.x;
    int lane = tid & 31;
    int warp = tid >> 5;
    int warp_m = warp & 1;        // 0..1
    int warp_n = warp >> 1;       // 0..3
    int g = lane >> 2;            // 0..7
    int q = lane & 3;             // 0..3
    int rowBase = blockIdx.y * 128;
    int colBase = blockIdx.x * 128;

    float c[4][4][4];             // [mi][ni][reg]
#pragma unroll
    for (int mi = 0; mi < 4; mi++)
#pragma unroll
        for (int ni = 0; ni < 4; ni++)
#pragma unroll
            for (int r = 0; r < 4; r++) c[mi][ni][r] = 0.f;

    for (int k0 = 0; k0 < HID; k0 += 32) {
        // A tile: 128x32 floats -> tf32, [m][k] padded
        {
            int m0 = tid >> 3;          // 0..31
            int kq = (tid & 7) * 4;     // 0,4,..28
#pragma unroll
            for (int i = 0; i < 4; i++) {
                int m = m0 + i * 32;
                int gr = rowBase + m;
                float4 v = (gr < N_NODES)
                    ? *(const float4*)&g_agg[(size_t)gr * HID + k0 + kq]
                    : make_float4(0.f, 0.f, 0.f, 0.f);
                uint32_t* dst = &As[m * AS_STRIDE + kq];
                dst[0] = f2tf32(v.x); dst[1] = f2tf32(v.y);
                dst[2] = f2tf32(v.z); dst[3] = f2tf32(v.w);
            }
        }
        // B tile: 32 k x 128 n floats -> tf32, [k][n] padded
        {
            int kk = tid >> 3;          // 0..31
            int nq = (tid & 7) * 4;
#pragma unroll
            for (int i = 0; i < 4; i++) {
                int n = nq + i * 32;
                float4 v = *(const float4*)&W[(size_t)(k0 + kk) * HID + colBase + n];
                uint32_t* dst = &Bs[kk * BS_STRIDE + n];
                dst[0] = f2tf32(v.x); dst[1] = f2tf32(v.y);
                dst[2] = f2tf32(v.z); dst[3] = f2tf32(v.w);
            }
        }
        __syncthreads();

#pragma unroll
        for (int ks = 0; ks < 4; ks++) {   // 4 k-steps of 8
            int kb = ks * 8;
            uint32_t a[4][4], b[4][2];
#pragma unroll
            for (int mi = 0; mi < 4; mi++) {
                int m = warp_m * 64 + mi * 16;
                const uint32_t* ap = &As[(m + g) * AS_STRIDE + kb + q];
                a[mi][0] = ap[0];
                a[mi][1] = ap[8 * AS_STRIDE];
                a[mi][2] = ap[4];
                a[mi][3] = ap[8 * AS_STRIDE + 4];
            }
#pragma unroll
            for (int ni = 0; ni < 4; ni++) {
                int n = warp_n * 32 + ni * 8;
                const uint32_t* bp = &Bs[(kb + q) * BS_STRIDE + n + g];
                b[ni][0] = bp[0];
                b[ni][1] = bp[4 * BS_STRIDE];
            }
#pragma unroll
            for (int mi = 0; mi < 4; mi++)
#pragma unroll
                for (int ni = 0; ni < 4; ni++) {
                    asm volatile(
                        "mma.sync.aligned.m16n8k8.row.col.f32.tf32.tf32.f32 "
                        "{%0,%1,%2,%3}, {%4,%5,%6,%7}, {%8,%9}, {%0,%1,%2,%3};"
                        : "+f"(c[mi][ni][0]), "+f"(c[mi][ni][1]),
                          "+f"(c[mi][ni][2]), "+f"(c[mi][ni][3])
                        : "r"(a[mi][0]), "r"(a[mi][1]), "r"(a[mi][2]), "r"(a[mi][3]),
                          "r"(b[ni][0]), "r"(b[ni][1]));
                }
        }
        __syncthreads();
    }

    // epilogue: c[mi][ni] regs map to rows (m+g, m+g+8), cols (n+2q, n+2q+1)
#pragma unroll
    for (int mi = 0; mi < 4; mi++) {
#pragma unroll
        for (int half = 0; half < 2; half++) {
            int r = rowBase + warp_m * 64 + mi * 16 + g + half * 8;
            if (r >= N_NODES) continue;
            float d = g_dinv[r];
#pragma unroll
            for (int ni = 0; ni < 4; ni++) {
                int cc = colBase + warp_n * 32 + ni * 8 + 2 * q;
                float v0 = d * c[mi][ni][half * 2 + 0] + bias[cc];
                float v1 = d * c[mi][ni][half * 2 + 1] + bias[cc + 1];
                if (WRITE_P) {
                    v0 = fmaxf(v0, 0.f) * d;
                    v1 = fmaxf(v1, 0.f) * d;
                    *(__half2*)&g_ph[(size_t)r * HID + cc] = __floats2half2_rn(v0, v1);
                } else {
                    *(float2*)&g_h[(size_t)r * HID + cc] = make_float2(v0, v1);
                }
            }
        }
    }
}

// ---- mean pool: block per graph, binary-search bounds (batch sorted),
//      row loop unrolled x4 for MLP ----
__global__ void k_pool(const int* __restrict__ batch) {
    int g = blockIdx.x;
    int j = threadIdx.x;  // 256
    int a = 0, b = N_NODES;
    while (a < b) { int m = (a + b) >> 1; if (batch[m] < g) a = m + 1; else b = m; }
    int lo = a;
    b = N_NODES;
    while (a < b) { int m = (a + b) >> 1; if (batch[m] < g + 1) a = m + 1; else b = m; }
    int hi = a;
    float s0 = 0.f, s1 = 0.f, s2 = 0.f, s3 = 0.f;
    int r = lo;
    for (; r + 4 <= hi; r += 4) {
        s0 += g_h[(size_t)(r + 0) * HID + j];
        s1 += g_h[(size_t)(r + 1) * HID + j];
        s2 += g_h[(size_t)(r + 2) * HID + j];
        s3 += g_h[(size_t)(r + 3) * HID + j];
    }
    for (; r < hi; r++) s0 += g_h[(size_t)r * HID + j];
    float acc = (s0 + s1) + (s2 + s3);
    g_pool[g * HID + j] = acc / fmaxf((float)(hi - lo), 1.f);
}

// ---- head: lin1+relu, lin2 ----
__global__ void k_head(const float* __restrict__ l1w, const float* __restrict__ l1b,
                       const float* __restrict__ l2w, const float* __restrict__ l2b,
                       float* __restrict__ out) {
    __shared__ float gv[HID];
    __shared__ float red[4];
    int g = blockIdx.x, t = threadIdx.x;  // 128 threads
    gv[t] = g_pool[g * HID + t];
    gv[t + 128] = g_pool[g * HID + t + 128];
    __syncthreads();
    float acc = l1b[t];
#pragma unroll 8
    for (int k = 0; k < HID; k++) acc += gv[k] * l1w[k * 128 + t];
    acc = fmaxf(acc, 0.f) * l2w[t];
#pragma unroll
    for (int o = 16; o; o >>= 1) acc += __shfl_down_sync(0xffffffffu, acc, o);
    if ((t & 31) == 0) red[t >> 5] = acc;
    __syncthreads();
    if (t == 0) out[g] = red[0] + red[1] + red[2] + red[3] + l2b[0];
}

extern "C" void kernel_launch(void* const* d_in, const int* in_sizes, int n_in,
                              void* d_out, int out_size) {
    const float* x     = (const float*)d_in[0];
    const int* ei      = (const int*)d_in[1];   // int32 (JAX x32 mode)
    const int* bat     = (const int*)d_in[2];   // int32
    const float* W1 = (const float*)d_in[3];
    const float* b1 = (const float*)d_in[4];
    const float* Wl[3] = {(const float*)d_in[5], (const float*)d_in[7], (const float*)d_in[9]};
    const float* bl[3] = {(const float*)d_in[6], (const float*)d_in[8], (const float*)d_in[10]};
    const float* l1w = (const float*)d_in[11];
    const float* l1b = (const float*)d_in[12];
    const float* l2w = (const float*)d_in[13];
    const float* l2b = (const float*)d_in[14];
    float* out = (float*)d_out;

    // degrees + norm + CSR (dst-major), parallel scan
    k_zero<<<(N_NODES + 255) / 256, 256>>>();
    k_count<<<(N_EDGES + 255) / 256, 256>>>(ei);
    k_rsqrt_px<<<(N_NODES + 255) / 256, 256>>>(x);
    k_blocksum<<<NBLK, 256>>>();
    k_scanb<<<1, 256>>>();
    k_scan3<<<NBLK, 256>>>();
    k_fill<<<(N_EDGES + 255) / 256, 256>>>(ei);

    // layer 1: fused 2-wide gather + 2->256 transform + relu*dinv prep (fp16 out)
    k_layer1<<<N_NODES, 256>>>(W1, b1);

    // layers 2..4: fp16 CSR gather (8-deep MLP) + tf32 tensor-core GEMM
    dim3 ggrid(HID / 128, (N_NODES + 127) / 128);
    k_gather<<<(N_NODES * 32 + 255) / 256, 256>>>();
    k_gemm<true><<<ggrid, 256>>>(Wl[0], bl[0]);
    k_gather<<<(N_NODES * 32 + 255) / 256, 256>>>();
    k_gemm<true><<<ggrid, 256>>>(Wl[1], bl[1]);
    k_gather<<<(N_NODES * 32 + 255) / 256, 256>>>();
    k_gemm<false><<<ggrid, 256>>>(Wl[2], bl[2]);

    // mean pool (no atomics) + MLP head
    k_pool<<<NG, 256>>>(bat);
    k_head<<<NG, 128>>>(l1w, l1b, l2w, l2b, out);
}